// round 9
// baseline (speedup 1.0000x reference)
#include <cuda_runtime.h>
#include <cstdint>

typedef unsigned long long u64;

#define B_   4096
#define XD   128
#define YD   64
#define T_   200
#define LAT  100
#define G3   300
#define CH   50
#define NBK  296           // 2 blocks per SM on 148 SMs, exactly balanced
#define NT   512           // 16 warps/block; 2 blocks/SM -> 8 warps/SMSP

// SMEM (float offsets), per block: 26572 floats = 106288 B (x2 = 212.6KB/SM)
// Dup buffers store each value twice at [.., 2r],[2r+1]; stride 36 keeps every
// row 16B-aligned so ulonglong2 LDS yields packed broadcast pairs.
#define OFF_BIH 0          // [300]
#define OFF_BHH 300        // [300]
#define OFF_BL1 600        // [100]
#define OFF_BL2 700        // [64]
#define OFF_HD  764        // [100][36] dup   3600
#define OFF_AXD 4364       // [128][36] dup   4608
#define OFF_S0  8972       // 11 partial slabs [16][100]
#define PSTR    1600
#define OFF_O1  OFF_S0     // [100][20] compact, overlays S0/S1 (barrier-separated)
#define SMEM_FLOATS 26572

__device__ __forceinline__ void fma2(u64 &d, u64 a, u64 b) {
    asm("fma.rn.f32x2 %0, %1, %2, %0;" : "+l"(d) : "l"(a), "l"(b));
}
__device__ __forceinline__ float2 unp(u64 v) {
    float2 f; asm("mov.b64 {%0, %1}, %2;" : "=f"(f.x), "=f"(f.y) : "l"(v));
    return f;
}
__device__ __forceinline__ float fsig(float x) {
    return __fdividef(1.0f, 1.0f + __expf(-x));
}
__device__ __forceinline__ float ftanh_(float x) {
    float e = __expf(2.0f * x);
    return 1.0f - __fdividef(2.0f, e + 1.0f);
}

// packed 8-row x 4-col accumulate: A = dup SMEM (stride 36, base offset r2=2*rr),
// W = gmem row-major stride G3 (4 floats = 2 packed col-pairs)
__device__ __forceinline__ void paccum8(
    u64 acc[8][2], const float* __restrict__ sa, int r2,
    const float* __restrict__ Wp, int k0, int k1)
{
#pragma unroll 2
    for (int k = k0; k < k1; k++) {
        const float* row = sa + k * 36 + r2;
        const ulonglong2 a01 = *(const ulonglong2*)(row);
        const ulonglong2 a23 = *(const ulonglong2*)(row + 4);
        const ulonglong2 a45 = *(const ulonglong2*)(row + 8);
        const ulonglong2 a67 = *(const ulonglong2*)(row + 12);
        const ulonglong2 w = __ldg((const ulonglong2*)&Wp[k * G3]);
        fma2(acc[0][0], a01.x, w.x); fma2(acc[0][1], a01.x, w.y);
        fma2(acc[1][0], a01.y, w.x); fma2(acc[1][1], a01.y, w.y);
        fma2(acc[2][0], a23.x, w.x); fma2(acc[2][1], a23.x, w.y);
        fma2(acc[3][0], a23.y, w.x); fma2(acc[3][1], a23.y, w.y);
        fma2(acc[4][0], a45.x, w.x); fma2(acc[4][1], a45.x, w.y);
        fma2(acc[5][0], a45.y, w.x); fma2(acc[5][1], a45.y, w.y);
        fma2(acc[6][0], a67.x, w.x); fma2(acc[6][1], a67.x, w.y);
        fma2(acc[7][0], a67.y, w.x); fma2(acc[7][1], a67.y, w.y);
    }
}
__device__ __forceinline__ void pzero8(u64 acc[8][2]) {
#pragma unroll
    for (int i = 0; i < 8; i++) { acc[i][0] = 0ull; acc[i][1] = 0ull; }
}
__device__ __forceinline__ void pstore8(float* __restrict__ dst, int rr, u64 acc[8][2]) {
#pragma unroll
    for (int i = 0; i < 8; i++) {
        ulonglong2 v; v.x = acc[i][0]; v.y = acc[i][1];
        *(ulonglong2*)&dst[(rr + i) * 100] = v;
    }
}

extern "C" __global__ void __launch_bounds__(NT, 2) gru_kernel(
    const float* __restrict__ x, const float* __restrict__ y, const void* __restrict__ ymask,
    const float* __restrict__ Wmu1, const float* __restrict__ bmu1,
    const float* __restrict__ Wmu2, const float* __restrict__ bmu2,
    const float* __restrict__ Wih, const float* __restrict__ bih,
    const float* __restrict__ Whh, const float* __restrict__ bhh,
    const float* __restrict__ Wl1, const float* __restrict__ bl1,
    const float* __restrict__ Wl2, const float* __restrict__ bl2,
    const float* __restrict__ Wc1, const float* __restrict__ bc1,
    const float* __restrict__ Wc2, const float* __restrict__ bc2,
    float* __restrict__ out, int has_cls)
{
    extern __shared__ float sm[];
    const int tid  = threadIdx.x;
    const int lane = tid & 31;
    const int wid  = tid >> 5;        // 0..15
    const int b0   = (B_ * blockIdx.x) / NBK;
    const int nr   = (B_ * (blockIdx.x + 1)) / NBK - b0;   // 13 or 14 rows
    const int j0   = lane * 4;        // lanes<25 cover 100 cols

    // ---- stage biases ----
    for (int i = tid; i < G3; i += NT) { sm[OFF_BIH + i] = bih[i]; sm[OFF_BHH + i] = bhh[i]; }
    for (int i = tid; i < LAT; i += NT) sm[OFF_BL1 + i] = bl1[i];
    for (int i = tid; i < YD;  i += NT) sm[OFF_BL2 + i] = bl2[i];

    // ---- mask dtype detection (uint8 / int32 / float32), deterministic ----
    const unsigned word = ((const unsigned*)ymask)[tid];
    const int big = __syncthreads_or((word & 0xFEFEFEFEu) != 0u);  // any byte > 1 -> f32
    const int odd = __syncthreads_or((word & 0xFFFFFF00u) != 0u);  // upper bytes set -> u8
    const int mode = big ? 2 : (odd ? 0 : 1);

    // ---- stage x into AXD (dup); rows >= nr zeroed ----
#pragma unroll
    for (int i = 0; i < 4; i++) {
        const int e = tid + NT * i;       // 2048 = 16r x 128k
        const int r = e & 15, k = e >> 4;
        const float v = (r < nr) ? __ldg(&x[(size_t)(b0 + r) * XD + k]) : 0.f;
        *(float2*)&sm[OFF_AXD + k * 36 + 2 * r] = make_float2(v, v);
    }
    __syncthreads();

    // ---- h0: tmp = tanh(x @ Wmu1 + bmu1) -> O1; h0 = tmp @ Wmu2 + bmu2 -> HD ----
    if (lane < 25) {
        float acc[4] = {0.f, 0.f, 0.f, 0.f};
#pragma unroll 4
        for (int k = 0; k < XD; k++) {
            const float a = sm[OFF_AXD + k * 36 + 2 * wid];
            const float4 wv = __ldg((const float4*)&Wmu1[k * LAT + j0]);
            acc[0] = fmaf(a, wv.x, acc[0]); acc[1] = fmaf(a, wv.y, acc[1]);
            acc[2] = fmaf(a, wv.z, acc[2]); acc[3] = fmaf(a, wv.w, acc[3]);
        }
        const float4 bb = __ldg((const float4*)&bmu1[j0]);
        sm[OFF_O1 + (j0 + 0) * 20 + wid] = ftanh_(acc[0] + bb.x);
        sm[OFF_O1 + (j0 + 1) * 20 + wid] = ftanh_(acc[1] + bb.y);
        sm[OFF_O1 + (j0 + 2) * 20 + wid] = ftanh_(acc[2] + bb.z);
        sm[OFF_O1 + (j0 + 3) * 20 + wid] = ftanh_(acc[3] + bb.w);
    }
    __syncthreads();

    float pv0, pv1, pmm0, pmm1;       // y/mask preloads for G4-fused teacher forcing
    auto preloadG4 = [&](int t) {
        const int row = lane & 15;
        const int jc  = (wid << 2) + ((lane >> 4) << 1);
        if (row < nr) {
            const size_t o0 = (size_t)(b0 + row) * (YD * T_) + (size_t)jc * T_ + t;
            const size_t o1 = o0 + T_;
            pv0 = __ldg(&y[o0]); pv1 = __ldg(&y[o1]);
            if (mode == 0) {
                pmm0 = (((const unsigned char*)ymask)[o0] != 0) ? 1.f : 0.f;
                pmm1 = (((const unsigned char*)ymask)[o1] != 0) ? 1.f : 0.f;
            } else if (mode == 1) {
                pmm0 = (((const int*)ymask)[o0] != 0) ? 1.f : 0.f;
                pmm1 = (((const int*)ymask)[o1] != 0) ? 1.f : 0.f;
            } else {
                pmm0 = (((const float*)ymask)[o0] != 0.f) ? 1.f : 0.f;
                pmm1 = (((const float*)ymask)[o1] != 0.f) ? 1.f : 0.f;
            }
        } else { pv0 = pv1 = pmm0 = pmm1 = 0.f; }
    };

    // h0 part 2 (reads O1, writes HD dup); plus initial teacher forcing (y_prev = 0)
    if (lane < 25) {
        float acc[4] = {0.f, 0.f, 0.f, 0.f};
#pragma unroll 4
        for (int k = 0; k < LAT; k++) {
            const float a = sm[OFF_O1 + k * 20 + wid];
            const float4 wv = __ldg((const float4*)&Wmu2[k * LAT + j0]);
            acc[0] = fmaf(a, wv.x, acc[0]); acc[1] = fmaf(a, wv.y, acc[1]);
            acc[2] = fmaf(a, wv.z, acc[2]); acc[3] = fmaf(a, wv.w, acc[3]);
        }
        const float4 bb = __ldg((const float4*)&bmu2[j0]);
        const float h0v = acc[0] + bb.x, h1v = acc[1] + bb.y;
        const float h2v = acc[2] + bb.z, h3v = acc[3] + bb.w;
        *(float2*)&sm[OFF_HD + (j0 + 0) * 36 + 2 * wid] = make_float2(h0v, h0v);
        *(float2*)&sm[OFF_HD + (j0 + 1) * 36 + 2 * wid] = make_float2(h1v, h1v);
        *(float2*)&sm[OFF_HD + (j0 + 2) * 36 + 2 * wid] = make_float2(h2v, h2v);
        *(float2*)&sm[OFF_HD + (j0 + 3) * 36 + 2 * wid] = make_float2(h3v, h3v);
    }
    preloadG4(0);
    {
        const int row = lane & 15;
        const int jc  = (wid << 2) + ((lane >> 4) << 1);
        const float yin0 = (pmm0 != 0.f) ? pv0 : 0.f;
        const float yin1 = (pmm1 != 0.f) ? pv1 : 0.f;
        *(float2*)&sm[OFF_AXD + (2 * jc + 0) * 36 + 2 * row] = make_float2(yin0, yin0);
        *(float2*)&sm[OFF_AXD + (2 * jc + 1) * 36 + 2 * row] = make_float2(pmm0, pmm0);
        *(float2*)&sm[OFF_AXD + (2 * jc + 2) * 36 + 2 * row] = make_float2(yin1, yin1);
        *(float2*)&sm[OFF_AXD + (2 * jc + 3) * 36 + 2 * row] = make_float2(pmm1, pmm1);
    }
    __syncthreads();

    // ================= main recurrence (4 barriers/step) =================
    for (int t = 0; t < T_; ++t) {
        // -- phase 1: packed FFMA2, 8 FFMA-balanced jobs x 2 row-halves --
        if (lane < 25) {
            u64 acc[8][2];
            pzero8(acc);
            const int job = wid >> 1;
            const int rr  = (wid & 1) * 8;
            const int r2  = rr * 2;
            float* S = sm + OFF_S0 + j0;
            switch (job) {
            case 0:  // r: AX[0,86)
                paccum8(acc, sm + OFF_AXD, r2, Wih + j0, 0, 86);
                pstore8(S + 0 * PSTR, rr, acc); break;
            case 1:  // r: AX[86,128) + H[0,44)
                paccum8(acc, sm + OFF_AXD, r2, Wih + j0, 86, XD);
                paccum8(acc, sm + OFF_HD,  r2, Whh + j0, 0, 44);
                pstore8(S + 1 * PSTR, rr, acc); break;
            case 2:  // r: H[44,100) ; z: AX[0,29)
                paccum8(acc, sm + OFF_HD, r2, Whh + j0, 44, LAT);
                pstore8(S + 2 * PSTR, rr, acc);
                pzero8(acc);
                paccum8(acc, sm + OFF_AXD, r2, Wih + 100 + j0, 0, 29);
                pstore8(S + 3 * PSTR, rr, acc); break;
            case 3:  // z: AX[29,115)
                paccum8(acc, sm + OFF_AXD, r2, Wih + 100 + j0, 29, 115);
                pstore8(S + 4 * PSTR, rr, acc); break;
            case 4:  // z: AX[115,128) + H[0,72)
                paccum8(acc, sm + OFF_AXD, r2, Wih + 100 + j0, 115, XD);
                paccum8(acc, sm + OFF_HD,  r2, Whh + 100 + j0, 0, 72);
                pstore8(S + 5 * PSTR, rr, acc); break;
            case 5:  // z: H[72,100) ; nx: AX[0,58)
                paccum8(acc, sm + OFF_HD, r2, Whh + 100 + j0, 72, LAT);
                pstore8(S + 6 * PSTR, rr, acc);
                pzero8(acc);
                paccum8(acc, sm + OFF_AXD, r2, Wih + 200 + j0, 0, 58);
                pstore8(S + 7 * PSTR, rr, acc); break;
            case 6:  // nx: AX[58,128) ; nh: H[0,15)
                paccum8(acc, sm + OFF_AXD, r2, Wih + 200 + j0, 58, XD);
                pstore8(S + 8 * PSTR, rr, acc);
                pzero8(acc);
                paccum8(acc, sm + OFF_HD, r2, Whh + 200 + j0, 0, 15);
                pstore8(S + 9 * PSTR, rr, acc); break;
            default: // nh: H[15,100)
                paccum8(acc, sm + OFF_HD, r2, Whh + 200 + j0, 15, LAT);
                pstore8(S + 10 * PSTR, rr, acc); break;
            }
        }
        __syncthreads();

        // -- preload y/mask(t+1) for G4-fused TF; then gates --
        if (t + 1 < T_) preloadG4(t + 1);
#pragma unroll
        for (int it = 0; it < 4; ++it) {
            const int idx = tid + NT * it;    // 1600 = 16r x 100j; ro == idx
            if (idx < 16 * LAT) {
                const int r = idx / LAT;
                const int j = idx - r * LAT;
                const float* S = sm + OFF_S0;
                const float g_r = S[idx] + S[PSTR + idx] + S[2 * PSTR + idx]
                                + sm[OFF_BIH + j] + sm[OFF_BHH + j];
                const float g_z = S[3 * PSTR + idx] + S[4 * PSTR + idx]
                                + S[5 * PSTR + idx] + S[6 * PSTR + idx]
                                + sm[OFF_BIH + 100 + j] + sm[OFF_BHH + 100 + j];
                const float gxn = S[7 * PSTR + idx] + S[8 * PSTR + idx]
                                + sm[OFF_BIH + 200 + j];
                const float ghn = S[9 * PSTR + idx] + S[10 * PSTR + idx]
                                + sm[OFF_BHH + 200 + j];
                const float rg = fsig(g_r);
                const float z  = fsig(g_z);
                const float n  = ftanh_(gxn + rg * ghn);
                const float hd = sm[OFF_HD + j * 36 + 2 * r];
                const float hn = (1.f - z) * n + z * hd;
                *(float2*)&sm[OFF_HD + j * 36 + 2 * r] = make_float2(hn, hn);
            }
        }
        __syncthreads();

        // -- GEMM3 packed: o1 = tanh(h @ Wl1 + bl1); 8 warps, col-pairs via FFMA2 --
        if (wid < 8 && lane < 25) {
            const int r3 = (wid & 3) << 2;
            const int jc = (wid >> 2) * 50 + 2 * lane;   // even col
            u64 acc0 = 0ull, acc1 = 0ull, acc2 = 0ull, acc3 = 0ull;
#pragma unroll 4
            for (int k = 0; k < LAT; k++) {
                const float* hrow = sm + OFF_HD + k * 36 + 2 * r3;
                const u64 a0 = *(const u64*)(hrow);
                const u64 a1 = *(const u64*)(hrow + 2);
                const u64 a2 = *(const u64*)(hrow + 4);
                const u64 a3 = *(const u64*)(hrow + 6);
                const u64 w = __ldg((const u64*)&Wl1[k * LAT + jc]);
                fma2(acc0, a0, w); fma2(acc1, a1, w);
                fma2(acc2, a2, w); fma2(acc3, a3, w);
            }
            const float ba = sm[OFF_BL1 + jc], bb = sm[OFF_BL1 + jc + 1];
            float2 v;
            v = unp(acc0);
            sm[OFF_O1 + jc * 20 + r3 + 0] = ftanh_(v.x + ba);
            sm[OFF_O1 + (jc + 1) * 20 + r3 + 0] = ftanh_(v.y + bb);
            v = unp(acc1);
            sm[OFF_O1 + jc * 20 + r3 + 1] = ftanh_(v.x + ba);
            sm[OFF_O1 + (jc + 1) * 20 + r3 + 1] = ftanh_(v.y + bb);
            v = unp(acc2);
            sm[OFF_O1 + jc * 20 + r3 + 2] = ftanh_(v.x + ba);
            sm[OFF_O1 + (jc + 1) * 20 + r3 + 2] = ftanh_(v.y + bb);
            v = unp(acc3);
            sm[OFF_O1 + jc * 20 + r3 + 3] = ftanh_(v.x + ba);
            sm[OFF_O1 + (jc + 1) * 20 + r3 + 3] = ftanh_(v.y + bb);
        }
        __syncthreads();

        // -- GEMM4 + fused teacher forcing: out_t = o1 @ Wl2 + bl2 --
        {
            const int row = lane & 15;                      // 0..15
            const int jc  = (wid << 2) + ((lane >> 4) << 1);// wid*4 + half*2
            float a0 = 0.f, a1 = 0.f;
#pragma unroll 4
            for (int k = 0; k < LAT; k++) {
                const float a = sm[OFF_O1 + k * 20 + row];
                const float2 wv = __ldg((const float2*)&Wl2[k * YD + jc]);
                a0 = fmaf(a, wv.x, a0); a1 = fmaf(a, wv.y, a1);
            }
            const float v0 = a0 + sm[OFF_BL2 + jc];
            const float v1 = a1 + sm[OFF_BL2 + jc + 1];
            if (row < nr) {
                float* op = out + (size_t)(b0 + row) * (YD * T_) + (size_t)jc * T_ + t;
                op[0]  = v0;
                op[T_] = v1;
            }
            if (t + 1 < T_) {
                const float yin0 = (pmm0 != 0.f) ? pv0 : v0;
                const float yin1 = (pmm1 != 0.f) ? pv1 : v1;
                *(float2*)&sm[OFF_AXD + (2 * jc + 0) * 36 + 2 * row] = make_float2(yin0, yin0);
                *(float2*)&sm[OFF_AXD + (2 * jc + 1) * 36 + 2 * row] = make_float2(pmm0, pmm0);
                *(float2*)&sm[OFF_AXD + (2 * jc + 2) * 36 + 2 * row] = make_float2(yin1, yin1);
                *(float2*)&sm[OFF_AXD + (2 * jc + 3) * 36 + 2 * row] = make_float2(pmm1, pmm1);
            }
        }
        __syncthreads();
    }

    // ---- classifier: sigmoid(relu(h_T @ Wc1 + bc1) @ Wc2 + bc2) ----
    if (has_cls) {
        float* scr = sm + OFF_S0;                            // free after loop
        for (int idx = tid; idx < 16 * CH; idx += NT) {      // 800 = 16r x 50c
            const int r = idx & 15, c = idx >> 4;
            float acc = __ldg(&bc1[c]);
            for (int k = 0; k < LAT; k++)
                acc = fmaf(sm[OFF_HD + k * 36 + 2 * r], __ldg(&Wc1[k * CH + c]), acc);
            scr[c * 16 + r] = fmaxf(acc, 0.f);
        }
        __syncthreads();
        if (tid < nr) {
            float acc = __ldg(&bc2[0]);
            for (int c = 0; c < CH; c++)
                acc = fmaf(scr[c * 16 + tid], __ldg(&Wc2[c]), acc);
            out[(size_t)B_ * YD * T_ + b0 + tid] = fsig(acc);
        }
    }
}

extern "C" void kernel_launch(void* const* d_in, const int* in_sizes, int n_in,
                              void* d_out, int out_size)
{
    cudaFuncSetAttribute(gru_kernel, cudaFuncAttributeMaxDynamicSharedMemorySize,
                         SMEM_FLOATS * (int)sizeof(float));
    const int has_cls = (out_size > B_ * YD * T_) ? 1 : 0;
    gru_kernel<<<NBK, NT, SMEM_FLOATS * sizeof(float)>>>(
        (const float*)d_in[0],   // x
        (const float*)d_in[1],   // y
        d_in[2],                 // y_mask (dtype auto-detected)
        (const float*)d_in[3],  (const float*)d_in[4],   // Wmu1, bmu1
        (const float*)d_in[5],  (const float*)d_in[6],   // Wmu2, bmu2
        (const float*)d_in[11], (const float*)d_in[12],  // Wih, bih
        (const float*)d_in[13], (const float*)d_in[14],  // Whh, bhh
        (const float*)d_in[15], (const float*)d_in[16],  // Wl1, bl1
        (const float*)d_in[17], (const float*)d_in[18],  // Wl2, bl2
        (const float*)d_in[19], (const float*)d_in[20],  // Wc1, bc1
        (const float*)d_in[21], (const float*)d_in[22],  // Wc2, bc2
        (float*)d_out, has_cls);
}

// round 10
// speedup vs baseline: 1.0860x; 1.0860x over previous
#include <cuda_runtime.h>
#include <cstdint>

#define B_   4096
#define XD   128
#define YD   64
#define T_   200
#define LAT  100
#define G3   300
#define CH   50
#define NBK  592           // 4 blocks per SM on 148 SMs, exactly balanced
#define NT   256           // 8 warps/block; 4 blocks/SM -> 8 warps/SMSP

// SMEM (float offsets), per block: 11788 floats = 47152 B (x4 = 188.6KB/SM)
#define OFF_BIH 0          // [300]
#define OFF_BHH 300        // [300]
#define OFF_BL1 600        // [100]
#define OFF_BL2 700        // [64]
#define OFF_H   764        // [100][12]  ([k][r])  1200
#define OFF_AX  1964       // [128][8]   ([k][r])  1024
#define OFF_S0  2988       // 11 partial slabs [8][100]
#define PSTR    800
#define OFF_O1  OFF_S0     // [100][12] overlays S0/S1 (barrier-separated)
#define SMEM_FLOATS 11788

__device__ __forceinline__ float fsig(float x) {
    return __fdividef(1.0f, 1.0f + __expf(-x));
}
__device__ __forceinline__ float ftanh_(float x) {
    float e = __expf(2.0f * x);
    return 1.0f - __fdividef(2.0f, e + 1.0f);
}

// 8-row x 4-col accumulate: A broadcast from SMEM (stride lda), W from gmem (stride G3)
__device__ __forceinline__ void accum8(
    float acc[8][4], const float* __restrict__ sa, int lda,
    const float* __restrict__ Wp, int k0, int k1)
{
#pragma unroll 2
    for (int k = k0; k < k1; k++) {
        const float4 a0 = *(const float4*)&sa[k * lda];
        const float4 a1 = *(const float4*)&sa[k * lda + 4];
        const float4 w  = __ldg((const float4*)&Wp[k * G3]);
        acc[0][0] = fmaf(a0.x, w.x, acc[0][0]); acc[0][1] = fmaf(a0.x, w.y, acc[0][1]);
        acc[0][2] = fmaf(a0.x, w.z, acc[0][2]); acc[0][3] = fmaf(a0.x, w.w, acc[0][3]);
        acc[1][0] = fmaf(a0.y, w.x, acc[1][0]); acc[1][1] = fmaf(a0.y, w.y, acc[1][1]);
        acc[1][2] = fmaf(a0.y, w.z, acc[1][2]); acc[1][3] = fmaf(a0.y, w.w, acc[1][3]);
        acc[2][0] = fmaf(a0.z, w.x, acc[2][0]); acc[2][1] = fmaf(a0.z, w.y, acc[2][1]);
        acc[2][2] = fmaf(a0.z, w.z, acc[2][2]); acc[2][3] = fmaf(a0.z, w.w, acc[2][3]);
        acc[3][0] = fmaf(a0.w, w.x, acc[3][0]); acc[3][1] = fmaf(a0.w, w.y, acc[3][1]);
        acc[3][2] = fmaf(a0.w, w.z, acc[3][2]); acc[3][3] = fmaf(a0.w, w.w, acc[3][3]);
        acc[4][0] = fmaf(a1.x, w.x, acc[4][0]); acc[4][1] = fmaf(a1.x, w.y, acc[4][1]);
        acc[4][2] = fmaf(a1.x, w.z, acc[4][2]); acc[4][3] = fmaf(a1.x, w.w, acc[4][3]);
        acc[5][0] = fmaf(a1.y, w.x, acc[5][0]); acc[5][1] = fmaf(a1.y, w.y, acc[5][1]);
        acc[5][2] = fmaf(a1.y, w.z, acc[5][2]); acc[5][3] = fmaf(a1.y, w.w, acc[5][3]);
        acc[6][0] = fmaf(a1.z, w.x, acc[6][0]); acc[6][1] = fmaf(a1.z, w.y, acc[6][1]);
        acc[6][2] = fmaf(a1.z, w.z, acc[6][2]); acc[6][3] = fmaf(a1.z, w.w, acc[6][3]);
        acc[7][0] = fmaf(a1.w, w.x, acc[7][0]); acc[7][1] = fmaf(a1.w, w.y, acc[7][1]);
        acc[7][2] = fmaf(a1.w, w.z, acc[7][2]); acc[7][3] = fmaf(a1.w, w.w, acc[7][3]);
    }
}
__device__ __forceinline__ void zero8(float acc[8][4]) {
#pragma unroll
    for (int i = 0; i < 8; i++)
#pragma unroll
        for (int c = 0; c < 4; c++) acc[i][c] = 0.f;
}
__device__ __forceinline__ void store8(float* __restrict__ dst, float acc[8][4]) {
#pragma unroll
    for (int i = 0; i < 8; i++)
        *(float4*)&dst[i * 100] =
            make_float4(acc[i][0], acc[i][1], acc[i][2], acc[i][3]);
}

extern "C" __global__ void __launch_bounds__(NT, 4) gru_kernel(
    const float* __restrict__ x, const float* __restrict__ y, const void* __restrict__ ymask,
    const float* __restrict__ Wmu1, const float* __restrict__ bmu1,
    const float* __restrict__ Wmu2, const float* __restrict__ bmu2,
    const float* __restrict__ Wih, const float* __restrict__ bih,
    const float* __restrict__ Whh, const float* __restrict__ bhh,
    const float* __restrict__ Wl1, const float* __restrict__ bl1,
    const float* __restrict__ Wl2, const float* __restrict__ bl2,
    const float* __restrict__ Wc1, const float* __restrict__ bc1,
    const float* __restrict__ Wc2, const float* __restrict__ bc2,
    float* __restrict__ out, int has_cls)
{
    extern __shared__ float sm[];
    const int tid  = threadIdx.x;
    const int lane = tid & 31;
    const int wid  = tid >> 5;        // 0..7
    const int b0   = (int)(((long long)B_ * blockIdx.x) / NBK);
    const int nr   = (int)(((long long)B_ * (blockIdx.x + 1)) / NBK) - b0;  // 6 or 7
    const int j0   = lane * 4;        // lanes<25 cover 100 cols

    // ---- stage biases ----
    for (int i = tid; i < G3; i += NT) { sm[OFF_BIH + i] = bih[i]; sm[OFF_BHH + i] = bhh[i]; }
    for (int i = tid; i < LAT; i += NT) sm[OFF_BL1 + i] = bl1[i];
    for (int i = tid; i < YD;  i += NT) sm[OFF_BL2 + i] = bl2[i];

    // ---- mask dtype detection (uint8 / int32 / float32), deterministic ----
    const unsigned word = ((const unsigned*)ymask)[tid];
    const int big = __syncthreads_or((word & 0xFEFEFEFEu) != 0u);  // any byte > 1 -> f32
    const int odd = __syncthreads_or((word & 0xFFFFFF00u) != 0u);  // upper bytes set -> u8
    const int mode = big ? 2 : (odd ? 0 : 1);

    // ---- stage x into AX ([k][8]); rows >= nr zeroed ----
#pragma unroll
    for (int i = 0; i < 4; i++) {
        const int e = tid + NT * i;       // 1024 = 8r x 128k
        const int r = e & 7, k = e >> 3;
        sm[OFF_AX + k * 8 + r] = (r < nr) ? __ldg(&x[(size_t)(b0 + r) * XD + k]) : 0.f;
    }
    __syncthreads();

    // ---- h0: tmp = tanh(x @ Wmu1 + bmu1) -> O1 (warp = row) ----
    if (lane < 25) {
        float acc[4] = {0.f, 0.f, 0.f, 0.f};
#pragma unroll 4
        for (int k = 0; k < XD; k++) {
            const float a = sm[OFF_AX + k * 8 + wid];
            const float4 wv = __ldg((const float4*)&Wmu1[k * LAT + j0]);
            acc[0] = fmaf(a, wv.x, acc[0]); acc[1] = fmaf(a, wv.y, acc[1]);
            acc[2] = fmaf(a, wv.z, acc[2]); acc[3] = fmaf(a, wv.w, acc[3]);
        }
        const float4 bb = __ldg((const float4*)&bmu1[j0]);
        sm[OFF_O1 + (j0 + 0) * 12 + wid] = ftanh_(acc[0] + bb.x);
        sm[OFF_O1 + (j0 + 1) * 12 + wid] = ftanh_(acc[1] + bb.y);
        sm[OFF_O1 + (j0 + 2) * 12 + wid] = ftanh_(acc[2] + bb.z);
        sm[OFF_O1 + (j0 + 3) * 12 + wid] = ftanh_(acc[3] + bb.w);
    }
    __syncthreads();

    // ---- y/mask preload registers for GEMM4-fused teacher forcing ----
    float pv0, pv1, pmm0, pmm1;
    const int g4row = tid & 7;
    const int g4jc  = (tid >> 3) << 1;      // 0,2,..,62
    auto preloadG4 = [&](int t) {
        if (g4row < nr) {
            const size_t o0 = (size_t)(b0 + g4row) * (YD * T_) + (size_t)g4jc * T_ + t;
            const size_t o1 = o0 + T_;
            pv0 = __ldg(&y[o0]); pv1 = __ldg(&y[o1]);
            if (mode == 0) {
                pmm0 = (((const unsigned char*)ymask)[o0] != 0) ? 1.f : 0.f;
                pmm1 = (((const unsigned char*)ymask)[o1] != 0) ? 1.f : 0.f;
            } else if (mode == 1) {
                pmm0 = (((const int*)ymask)[o0] != 0) ? 1.f : 0.f;
                pmm1 = (((const int*)ymask)[o1] != 0) ? 1.f : 0.f;
            } else {
                pmm0 = (((const float*)ymask)[o0] != 0.f) ? 1.f : 0.f;
                pmm1 = (((const float*)ymask)[o1] != 0.f) ? 1.f : 0.f;
            }
        } else { pv0 = pv1 = pmm0 = pmm1 = 0.f; }
    };

    // ---- h0 part 2: H = tmp @ Wmu2 + bmu2 ----
    if (lane < 25) {
        float acc[4] = {0.f, 0.f, 0.f, 0.f};
#pragma unroll 4
        for (int k = 0; k < LAT; k++) {
            const float a = sm[OFF_O1 + k * 12 + wid];
            const float4 wv = __ldg((const float4*)&Wmu2[k * LAT + j0]);
            acc[0] = fmaf(a, wv.x, acc[0]); acc[1] = fmaf(a, wv.y, acc[1]);
            acc[2] = fmaf(a, wv.z, acc[2]); acc[3] = fmaf(a, wv.w, acc[3]);
        }
        const float4 bb = __ldg((const float4*)&bmu2[j0]);
        sm[OFF_H + (j0 + 0) * 12 + wid] = acc[0] + bb.x;
        sm[OFF_H + (j0 + 1) * 12 + wid] = acc[1] + bb.y;
        sm[OFF_H + (j0 + 2) * 12 + wid] = acc[2] + bb.z;
        sm[OFF_H + (j0 + 3) * 12 + wid] = acc[3] + bb.w;
    }
    // initial teacher forcing into AX (y_prev = 0 at t=0)
    preloadG4(0);
    {
        const float yin0 = (pmm0 != 0.f) ? pv0 : 0.f;
        const float yin1 = (pmm1 != 0.f) ? pv1 : 0.f;
        sm[OFF_AX + (2 * g4jc + 0) * 8 + g4row] = yin0;
        sm[OFF_AX + (2 * g4jc + 1) * 8 + g4row] = pmm0;
        sm[OFF_AX + (2 * g4jc + 2) * 8 + g4row] = yin1;
        sm[OFF_AX + (2 * g4jc + 3) * 8 + g4row] = pmm1;
    }
    __syncthreads();

    // ================= main recurrence (4 barriers/step) =================
    for (int t = 0; t < T_; ++t) {
        // -- phase 1: 8 FFMA-balanced jobs (85-86 k-iters), one warp each, 8-row tiles --
        if (lane < 25) {
            float acc[8][4];
            zero8(acc);
            float* S = sm + OFF_S0 + j0;
            switch (wid) {
            case 0:  // r: AX[0,86)
                accum8(acc, sm + OFF_AX, 8, Wih + j0, 0, 86);
                store8(S + 0 * PSTR, acc); break;
            case 1:  // r: AX[86,128) + H[0,44)
                accum8(acc, sm + OFF_AX, 8,  Wih + j0, 86, XD);
                accum8(acc, sm + OFF_H,  12, Whh + j0, 0, 44);
                store8(S + 1 * PSTR, acc); break;
            case 2:  // r: H[44,100) ; z: AX[0,29)
                accum8(acc, sm + OFF_H, 12, Whh + j0, 44, LAT);
                store8(S + 2 * PSTR, acc);
                zero8(acc);
                accum8(acc, sm + OFF_AX, 8, Wih + 100 + j0, 0, 29);
                store8(S + 3 * PSTR, acc); break;
            case 3:  // z: AX[29,115)
                accum8(acc, sm + OFF_AX, 8, Wih + 100 + j0, 29, 115);
                store8(S + 4 * PSTR, acc); break;
            case 4:  // z: AX[115,128) + H[0,72)
                accum8(acc, sm + OFF_AX, 8,  Wih + 100 + j0, 115, XD);
                accum8(acc, sm + OFF_H,  12, Whh + 100 + j0, 0, 72);
                store8(S + 5 * PSTR, acc); break;
            case 5:  // z: H[72,100) ; nx: AX[0,58)
                accum8(acc, sm + OFF_H, 12, Whh + 100 + j0, 72, LAT);
                store8(S + 6 * PSTR, acc);
                zero8(acc);
                accum8(acc, sm + OFF_AX, 8, Wih + 200 + j0, 0, 58);
                store8(S + 7 * PSTR, acc); break;
            case 6:  // nx: AX[58,128) ; nh: H[0,15)
                accum8(acc, sm + OFF_AX, 8, Wih + 200 + j0, 58, XD);
                store8(S + 8 * PSTR, acc);
                zero8(acc);
                accum8(acc, sm + OFF_H, 12, Whh + 200 + j0, 0, 15);
                store8(S + 9 * PSTR, acc); break;
            default: // nh: H[15,100)
                accum8(acc, sm + OFF_H, 12, Whh + 200 + j0, 15, LAT);
                store8(S + 10 * PSTR, acc); break;
            }
        }
        __syncthreads();

        // -- preload y/mask(t+1); gates: r,z = sigmoid; n = tanh(gxn + r*ghn) --
        if (t + 1 < T_) preloadG4(t + 1);
#pragma unroll
        for (int it = 0; it < 4; ++it) {
            const int idx = tid + NT * it;    // 800 = 8r x 100j; idx == r*100+j
            if (idx < 8 * LAT) {
                const int r = idx / LAT;
                const int j = idx - r * LAT;
                const float* S = sm + OFF_S0;
                const float g_r = S[idx] + S[PSTR + idx] + S[2 * PSTR + idx]
                                + sm[OFF_BIH + j] + sm[OFF_BHH + j];
                const float g_z = S[3 * PSTR + idx] + S[4 * PSTR + idx]
                                + S[5 * PSTR + idx] + S[6 * PSTR + idx]
                                + sm[OFF_BIH + 100 + j] + sm[OFF_BHH + 100 + j];
                const float gxn = S[7 * PSTR + idx] + S[8 * PSTR + idx]
                                + sm[OFF_BIH + 200 + j];
                const float ghn = S[9 * PSTR + idx] + S[10 * PSTR + idx]
                                + sm[OFF_BHH + 200 + j];
                const float rg = fsig(g_r);
                const float z  = fsig(g_z);
                const float n  = ftanh_(gxn + rg * ghn);
                const float hd = sm[OFF_H + j * 12 + r];
                sm[OFF_H + j * 12 + r] = (1.f - z) * n + z * hd;
            }
        }
        __syncthreads();

        // -- GEMM3: o1 = tanh(h @ Wl1 + bl1); 2 row-quads x 4 col-chunks, scalar W --
        if (lane < 25) {
            const int r3 = (wid & 1) << 2;   // 0 or 4
            const int jc = (wid >> 1) * 25 + lane;
            float a0 = 0.f, a1 = 0.f, a2 = 0.f, a3 = 0.f;
#pragma unroll 4
            for (int k = 0; k < LAT; k++) {
                const float4 a = *(const float4*)&sm[OFF_H + k * 12 + r3];
                const float w = __ldg(&Wl1[k * LAT + jc]);
                a0 = fmaf(a.x, w, a0); a1 = fmaf(a.y, w, a1);
                a2 = fmaf(a.z, w, a2); a3 = fmaf(a.w, w, a3);
            }
            const float bb = sm[OFF_BL1 + jc];
            sm[OFF_O1 + jc * 12 + r3 + 0] = ftanh_(a0 + bb);
            sm[OFF_O1 + jc * 12 + r3 + 1] = ftanh_(a1 + bb);
            sm[OFF_O1 + jc * 12 + r3 + 2] = ftanh_(a2 + bb);
            sm[OFF_O1 + jc * 12 + r3 + 3] = ftanh_(a3 + bb);
        }
        __syncthreads();

        // -- GEMM4 + fused teacher forcing: out_t = o1 @ Wl2 + bl2 --
        {
            float a0 = 0.f, a1 = 0.f;
#pragma unroll 4
            for (int k = 0; k < LAT; k++) {
                const float a = sm[OFF_O1 + k * 12 + g4row];
                const float2 wv = __ldg((const float2*)&Wl2[k * YD + g4jc]);
                a0 = fmaf(a, wv.x, a0); a1 = fmaf(a, wv.y, a1);
            }
            const float v0 = a0 + sm[OFF_BL2 + g4jc];
            const float v1 = a1 + sm[OFF_BL2 + g4jc + 1];
            if (g4row < nr) {
                float* op = out + (size_t)(b0 + g4row) * (YD * T_) + (size_t)g4jc * T_ + t;
                op[0]  = v0;
                op[T_] = v1;
            }
            if (t + 1 < T_) {
                const float yin0 = (pmm0 != 0.f) ? pv0 : v0;
                const float yin1 = (pmm1 != 0.f) ? pv1 : v1;
                sm[OFF_AX + (2 * g4jc + 0) * 8 + g4row] = yin0;
                sm[OFF_AX + (2 * g4jc + 1) * 8 + g4row] = pmm0;
                sm[OFF_AX + (2 * g4jc + 2) * 8 + g4row] = yin1;
                sm[OFF_AX + (2 * g4jc + 3) * 8 + g4row] = pmm1;
            }
        }
        __syncthreads();
    }

    // ---- classifier: sigmoid(relu(h_T @ Wc1 + bc1) @ Wc2 + bc2) ----
    if (has_cls) {
        float* scr = sm + OFF_S0 + 4 * PSTR;                 // free after loop
        for (int idx = tid; idx < 8 * CH; idx += NT) {       // 400 = 8r x 50c
            const int r = idx & 7, c = idx >> 3;
            float acc = __ldg(&bc1[c]);
            for (int k = 0; k < LAT; k++)
                acc = fmaf(sm[OFF_H + k * 12 + r], __ldg(&Wc1[k * CH + c]), acc);
            scr[c * 8 + r] = fmaxf(acc, 0.f);
        }
        __syncthreads();
        if (tid < nr) {
            float acc = __ldg(&bc2[0]);
            for (int c = 0; c < CH; c++)
                acc = fmaf(scr[c * 8 + tid], __ldg(&Wc2[c]), acc);
            out[(size_t)B_ * YD * T_ + b0 + tid] = fsig(acc);
        }
    }
}

extern "C" void kernel_launch(void* const* d_in, const int* in_sizes, int n_in,
                              void* d_out, int out_size)
{
    cudaFuncSetAttribute(gru_kernel, cudaFuncAttributeMaxDynamicSharedMemorySize,
                         SMEM_FLOATS * (int)sizeof(float));
    const int has_cls = (out_size > B_ * YD * T_) ? 1 : 0;
    gru_kernel<<<NBK, NT, SMEM_FLOATS * sizeof(float)>>>(
        (const float*)d_in[0],   // x
        (const float*)d_in[1],   // y
        d_in[2],                 // y_mask (dtype auto-detected)
        (const float*)d_in[3],  (const float*)d_in[4],   // Wmu1, bmu1
        (const float*)d_in[5],  (const float*)d_in[6],   // Wmu2, bmu2
        (const float*)d_in[11], (const float*)d_in[12],  // Wih, bih
        (const float*)d_in[13], (const float*)d_in[14],  // Whh, bhh
        (const float*)d_in[15], (const float*)d_in[16],  // Wl1, bl1
        (const float*)d_in[17], (const float*)d_in[18],  // Wl2, bl2
        (const float*)d_in[19], (const float*)d_in[20],  // Wc1, bc1
        (const float*)d_in[21], (const float*)d_in[22],  // Wc2, bc2
        (float*)d_out, has_cls);
}

// round 11
// speedup vs baseline: 1.1147x; 1.0264x over previous
#include <cuda_runtime.h>
#include <cstdint>

#define B_   4096
#define XD   128
#define YD   64
#define T_   200
#define LAT  100
#define G3   300
#define CH   50
#define NBK  296           // 2 blocks per SM on 148 SMs, exactly balanced
#define NT   512           // 16 warps/block; 2 blocks/SM -> 8 warps/SMSP

// SMEM layout (float offsets), per block: 24204 floats = 96816 bytes
#define OFF_BIH 0          // [300]  (folded: [0,200)=bih+bhh, [200,300)=bih)
#define OFF_BHH 300        // [300]
#define OFF_BL1 600        // [100]
#define OFF_BL2 700        // [64]
#define OFF_H   764        // [100][20]  ([k][r])   2000
#define OFF_AX  2764       // [128][16]  ([k][r])   2048
#define OFF_YP  4812       // [64][17]   ([d][r])   1088
#define OFF_S0  5900       // 11 partial slabs [16][100]
#define PSTR    1600
#define OFF_O1  OFF_S0     // [100][20] overlays S0/S1 (barrier-separated)
#define SMEM_FLOATS (OFF_S0 + 11 * PSTR)   // 24204

__device__ __forceinline__ float rcp_(float x) {
    float r; asm("rcp.approx.f32 %0, %1;" : "=f"(r) : "f"(x)); return r;
}
// 4 reciprocals for the price of 1 MUFU (prefix products + unwind)
__device__ __forceinline__ void rcp4(const float d[4], float inv[4]) {
    const float p1 = d[0] * d[1], p2 = p1 * d[2], p3 = p2 * d[3];
    const float q3 = rcp_(p3);
    inv[3] = q3 * p2;
    const float q2 = q3 * d[3];
    inv[2] = q2 * p1;
    const float q1 = q2 * d[2];
    inv[1] = q1 * d[0];
    inv[0] = q1 * d[1];
}
__device__ __forceinline__ float fsig(float x) {
    return __fdividef(1.0f, 1.0f + __expf(-x));
}
__device__ __forceinline__ float ftanh_(float x) {
    float e = __expf(2.0f * x);
    return 1.0f - __fdividef(2.0f, e + 1.0f);
}

// 8-row x 4-col accumulate: A broadcast from SMEM (stride lda), W from gmem (stride G3)
__device__ __forceinline__ void accum8(
    float acc[8][4], const float* __restrict__ sa, int lda, int r0,
    const float* __restrict__ Wp, int k0, int k1)
{
#pragma unroll 2
    for (int k = k0; k < k1; k++) {
        const float4 a0 = *(const float4*)&sa[k * lda + r0];
        const float4 a1 = *(const float4*)&sa[k * lda + r0 + 4];
        const float4 w  = __ldg((const float4*)&Wp[k * G3]);
        acc[0][0] = fmaf(a0.x, w.x, acc[0][0]); acc[0][1] = fmaf(a0.x, w.y, acc[0][1]);
        acc[0][2] = fmaf(a0.x, w.z, acc[0][2]); acc[0][3] = fmaf(a0.x, w.w, acc[0][3]);
        acc[1][0] = fmaf(a0.y, w.x, acc[1][0]); acc[1][1] = fmaf(a0.y, w.y, acc[1][1]);
        acc[1][2] = fmaf(a0.y, w.z, acc[1][2]); acc[1][3] = fmaf(a0.y, w.w, acc[1][3]);
        acc[2][0] = fmaf(a0.z, w.x, acc[2][0]); acc[2][1] = fmaf(a0.z, w.y, acc[2][1]);
        acc[2][2] = fmaf(a0.z, w.z, acc[2][2]); acc[2][3] = fmaf(a0.z, w.w, acc[2][3]);
        acc[3][0] = fmaf(a0.w, w.x, acc[3][0]); acc[3][1] = fmaf(a0.w, w.y, acc[3][1]);
        acc[3][2] = fmaf(a0.w, w.z, acc[3][2]); acc[3][3] = fmaf(a0.w, w.w, acc[3][3]);
        acc[4][0] = fmaf(a1.x, w.x, acc[4][0]); acc[4][1] = fmaf(a1.x, w.y, acc[4][1]);
        acc[4][2] = fmaf(a1.x, w.z, acc[4][2]); acc[4][3] = fmaf(a1.x, w.w, acc[4][3]);
        acc[5][0] = fmaf(a1.y, w.x, acc[5][0]); acc[5][1] = fmaf(a1.y, w.y, acc[5][1]);
        acc[5][2] = fmaf(a1.y, w.z, acc[5][2]); acc[5][3] = fmaf(a1.y, w.w, acc[5][3]);
        acc[6][0] = fmaf(a1.z, w.x, acc[6][0]); acc[6][1] = fmaf(a1.z, w.y, acc[6][1]);
        acc[6][2] = fmaf(a1.z, w.z, acc[6][2]); acc[6][3] = fmaf(a1.z, w.w, acc[6][3]);
        acc[7][0] = fmaf(a1.w, w.x, acc[7][0]); acc[7][1] = fmaf(a1.w, w.y, acc[7][1]);
        acc[7][2] = fmaf(a1.w, w.z, acc[7][2]); acc[7][3] = fmaf(a1.w, w.w, acc[7][3]);
    }
}
__device__ __forceinline__ void zero8(float acc[8][4]) {
#pragma unroll
    for (int i = 0; i < 8; i++)
#pragma unroll
        for (int c = 0; c < 4; c++) acc[i][c] = 0.f;
}
__device__ __forceinline__ void store8(float* __restrict__ dst, int rr, float acc[8][4]) {
#pragma unroll
    for (int i = 0; i < 8; i++)
        *(float4*)&dst[(rr + i) * 100] =
            make_float4(acc[i][0], acc[i][1], acc[i][2], acc[i][3]);
}

extern "C" __global__ void __launch_bounds__(NT, 2) gru_kernel(
    const float* __restrict__ x, const float* __restrict__ y, const void* __restrict__ ymask,
    const float* __restrict__ Wmu1, const float* __restrict__ bmu1,
    const float* __restrict__ Wmu2, const float* __restrict__ bmu2,
    const float* __restrict__ Wih, const float* __restrict__ bih,
    const float* __restrict__ Whh, const float* __restrict__ bhh,
    const float* __restrict__ Wl1, const float* __restrict__ bl1,
    const float* __restrict__ Wl2, const float* __restrict__ bl2,
    const float* __restrict__ Wc1, const float* __restrict__ bc1,
    const float* __restrict__ Wc2, const float* __restrict__ bc2,
    float* __restrict__ out, int has_cls)
{
    extern __shared__ float sm[];
    const int tid  = threadIdx.x;
    const int lane = tid & 31;
    const int wid  = tid >> 5;        // 0..15
    const int b0   = (B_ * blockIdx.x) / NBK;
    const int nr   = (B_ * (blockIdx.x + 1)) / NBK - b0;   // 13 or 14 rows
    const int j0   = lane * 4;        // lanes<25 cover 100 cols

    // ---- stage biases (fold bih+bhh for r,z chunks); zero y_prev ----
    for (int i = tid; i < G3; i += NT) {
        sm[OFF_BIH + i] = (i < 200) ? bih[i] + bhh[i] : bih[i];
        sm[OFF_BHH + i] = bhh[i];
    }
    for (int i = tid; i < LAT; i += NT) sm[OFF_BL1 + i] = bl1[i];
    for (int i = tid; i < YD;  i += NT) sm[OFF_BL2 + i] = bl2[i];
    for (int i = tid; i < YD * 17; i += NT) sm[OFF_YP + i] = 0.f;

    // ---- mask dtype detection (uint8 / int32 / float32), deterministic ----
    const unsigned word = ((const unsigned*)ymask)[tid];
    const int big = __syncthreads_or((word & 0xFEFEFEFEu) != 0u);  // any byte > 1 -> f32
    const int odd = __syncthreads_or((word & 0xFFFFFF00u) != 0u);  // upper bytes set -> u8
    const int mode = big ? 2 : (odd ? 0 : 1);

    // ---- stage x into AX ([k][16]); rows >= nr zeroed ----
#pragma unroll
    for (int i = 0; i < 4; i++) {
        const int e = tid + NT * i;       // 2048 = 16r x 128k
        const int r = e & 15, k = e >> 4;
        sm[OFF_AX + k * 16 + r] = (r < nr) ? __ldg(&x[(size_t)(b0 + r) * XD + k]) : 0.f;
    }
    __syncthreads();

    // ---- h0: tmp = tanh(x @ Wmu1 + bmu1) -> O1; h0 = tmp @ Wmu2 + bmu2 -> H ----
    if (lane < 25) {
        float acc[4] = {0.f, 0.f, 0.f, 0.f};
#pragma unroll 4
        for (int k = 0; k < XD; k++) {
            const float a = sm[OFF_AX + k * 16 + wid];
            const float4 wv = __ldg((const float4*)&Wmu1[k * LAT + j0]);
            acc[0] = fmaf(a, wv.x, acc[0]); acc[1] = fmaf(a, wv.y, acc[1]);
            acc[2] = fmaf(a, wv.z, acc[2]); acc[3] = fmaf(a, wv.w, acc[3]);
        }
        const float4 bb = __ldg((const float4*)&bmu1[j0]);
        sm[OFF_O1 + (j0 + 0) * 20 + wid] = ftanh_(acc[0] + bb.x);
        sm[OFF_O1 + (j0 + 1) * 20 + wid] = ftanh_(acc[1] + bb.y);
        sm[OFF_O1 + (j0 + 2) * 20 + wid] = ftanh_(acc[2] + bb.z);
        sm[OFF_O1 + (j0 + 3) * 20 + wid] = ftanh_(acc[3] + bb.w);
    }
    __syncthreads();
    if (lane < 25) {
        float acc[4] = {0.f, 0.f, 0.f, 0.f};
#pragma unroll 4
        for (int k = 0; k < LAT; k++) {
            const float a = sm[OFF_O1 + k * 20 + wid];
            const float4 wv = __ldg((const float4*)&Wmu2[k * LAT + j0]);
            acc[0] = fmaf(a, wv.x, acc[0]); acc[1] = fmaf(a, wv.y, acc[1]);
            acc[2] = fmaf(a, wv.z, acc[2]); acc[3] = fmaf(a, wv.w, acc[3]);
        }
        const float4 bb = __ldg((const float4*)&bmu2[j0]);
        sm[OFF_H + (j0 + 0) * 20 + wid] = acc[0] + bb.x;
        sm[OFF_H + (j0 + 1) * 20 + wid] = acc[1] + bb.y;
        sm[OFF_H + (j0 + 2) * 20 + wid] = acc[2] + bb.z;
        sm[OFF_H + (j0 + 3) * 20 + wid] = acc[3] + bb.w;
    }

    // ---- prefetch y/mask for t=0 ----
    float yv[2], mfv[2];
    auto preload = [&](int t) {
#pragma unroll
        for (int i = 0; i < 2; i++) {
            const int e = tid + NT * i;   // 1024 = 16r x 64d
            const int r = e & 15, d = e >> 4;
            if (r < nr) {
                const size_t off = (size_t)(b0 + r) * (YD * T_) + (size_t)d * T_ + t;
                yv[i] = __ldg(&y[off]);
                float m;
                if (mode == 0)      m = (((const unsigned char*)ymask)[off] != 0) ? 1.f : 0.f;
                else if (mode == 1) m = (((const int*)ymask)[off] != 0) ? 1.f : 0.f;
                else                m = (((const float*)ymask)[off] != 0.f) ? 1.f : 0.f;
                mfv[i] = m;
            } else { yv[i] = 0.f; mfv[i] = 0.f; }
        }
    };
    preload(0);
    __syncthreads();

    // ================= main recurrence =================
    for (int t = 0; t < T_; ++t) {
        // -- teacher forcing -> AX ([k][16], k interleaved value/mask) --
#pragma unroll
        for (int i = 0; i < 2; i++) {
            const int e = tid + NT * i;
            const int r = e & 15, d = e >> 4;
            const float m  = mfv[i];
            const float yp = sm[OFF_YP + d * 17 + r];
            const float yin = (m != 0.f) ? yv[i] : yp;
            sm[OFF_AX + (2 * d) * 16 + r]     = yin;
            sm[OFF_AX + (2 * d + 1) * 16 + r] = m;
        }
        if (t + 1 < T_) preload(t + 1);
        __syncthreads();

        // -- phase 1: 8 FFMA-balanced jobs x 2 row-halves, 8-row microtiles --
        if (lane < 25) {
            float acc[8][4];
            zero8(acc);
            const int job = wid >> 1;
            const int rr  = (wid & 1) * 8;
            float* S = sm + OFF_S0 + j0;
            switch (job) {
            case 0:  // r: AX[0,86)
                accum8(acc, sm + OFF_AX, 16, rr, Wih + j0, 0, 86);
                store8(S + 0 * PSTR, rr, acc); break;
            case 1:  // r: AX[86,128) + H[0,44)
                accum8(acc, sm + OFF_AX, 16, rr, Wih + j0, 86, XD);
                accum8(acc, sm + OFF_H,  20, rr, Whh + j0, 0, 44);
                store8(S + 1 * PSTR, rr, acc); break;
            case 2:  // r: H[44,100) ; z: AX[0,29)
                accum8(acc, sm + OFF_H, 20, rr, Whh + j0, 44, LAT);
                store8(S + 2 * PSTR, rr, acc);
                zero8(acc);
                accum8(acc, sm + OFF_AX, 16, rr, Wih + 100 + j0, 0, 29);
                store8(S + 3 * PSTR, rr, acc); break;
            case 3:  // z: AX[29,115)
                accum8(acc, sm + OFF_AX, 16, rr, Wih + 100 + j0, 29, 115);
                store8(S + 4 * PSTR, rr, acc); break;
            case 4:  // z: AX[115,128) + H[0,72)
                accum8(acc, sm + OFF_AX, 16, rr, Wih + 100 + j0, 115, XD);
                accum8(acc, sm + OFF_H,  20, rr, Whh + 100 + j0, 0, 72);
                store8(S + 5 * PSTR, rr, acc); break;
            case 5:  // z: H[72,100) ; nx: AX[0,58)
                accum8(acc, sm + OFF_H, 20, rr, Whh + 100 + j0, 72, LAT);
                store8(S + 6 * PSTR, rr, acc);
                zero8(acc);
                accum8(acc, sm + OFF_AX, 16, rr, Wih + 200 + j0, 0, 58);
                store8(S + 7 * PSTR, rr, acc); break;
            case 6:  // nx: AX[58,128) ; nh: H[0,15)
                accum8(acc, sm + OFF_AX, 16, rr, Wih + 200 + j0, 58, XD);
                store8(S + 8 * PSTR, rr, acc);
                zero8(acc);
                accum8(acc, sm + OFF_H, 20, rr, Whh + 200 + j0, 0, 15);
                store8(S + 9 * PSTR, rr, acc); break;
            default: // nh: H[15,100)
                accum8(acc, sm + OFF_H, 20, rr, Whh + 200 + j0, 15, LAT);
                store8(S + 10 * PSTR, rr, acc); break;
            }
        }
        __syncthreads();

        // -- gates: thread = (j, 4 rows); batched-RCP transcendentals (3.75 MUFU/elem) --
        if (tid < 400) {
            const int j  = tid % 100;
            const int r0 = (tid / 100) << 2;
            const int base = r0 * 100 + j;
            const float* S = sm + OFF_S0;
            const float BR  = sm[OFF_BIH + j];          // bih+bhh folded
            const float BZ  = sm[OFF_BIH + 100 + j];    // bih+bhh folded
            const float BNX = sm[OFF_BIH + 200 + j];
            const float BNH = sm[OFF_BHH + 200 + j];
            float gr[4], gz[4], gx[4], gh[4];
#pragma unroll
            for (int i = 0; i < 4; i++) {
                const int idx = base + i * 100;
                gr[i] = S[idx] + S[PSTR + idx] + S[2 * PSTR + idx] + BR;
                gz[i] = S[3 * PSTR + idx] + S[4 * PSTR + idx]
                      + S[5 * PSTR + idx] + S[6 * PSTR + idx] + BZ;
                gx[i] = S[7 * PSTR + idx] + S[8 * PSTR + idx] + BNX;
                gh[i] = S[9 * PSTR + idx] + S[10 * PSTR + idx] + BNH;
            }
            float dr[4], dz[4], rg[4], zg[4];
#pragma unroll
            for (int i = 0; i < 4; i++) {
                dr[i] = 1.f + __expf(-fminf(fmaxf(gr[i], -15.f), 15.f));
                dz[i] = 1.f + __expf(-fminf(fmaxf(gz[i], -15.f), 15.f));
            }
            rcp4(dr, rg);           // rg = sigmoid(gr)
            rcp4(dz, zg);           // zg = sigmoid(gz)
            float dn[4], iv[4];
#pragma unroll
            for (int i = 0; i < 4; i++) {
                float u = gx[i] + rg[i] * gh[i];
                u = fminf(fmaxf(u, -10.f), 10.f);
                dn[i] = __expf(2.f * u) + 1.f;
            }
            rcp4(dn, iv);           // tanh(u) = 1 - 2*iv
            const float4 hv = *(const float4*)&sm[OFF_H + j * 20 + r0];
            const float ho[4] = {hv.x, hv.y, hv.z, hv.w};
            float hn[4];
#pragma unroll
            for (int i = 0; i < 4; i++) {
                const float n = 1.f - 2.f * iv[i];
                hn[i] = (1.f - zg[i]) * n + zg[i] * ho[i];
            }
            *(float4*)&sm[OFF_H + j * 20 + r0] = make_float4(hn[0], hn[1], hn[2], hn[3]);
        }
        __syncthreads();

        // -- GEMM3: o1 = tanh(h @ Wl1 + bl1); batched tanh (1.25 MUFU/elem) --
        if (lane < 25) {
            const int q3 = wid & 3;          // row quad
            const int c3 = wid >> 2;         // col chunk of 25
            const int r3 = q3 << 2;
            const int jc = c3 * 25 + lane;
            float a0 = 0.f, a1 = 0.f, a2 = 0.f, a3 = 0.f;
#pragma unroll 4
            for (int k = 0; k < LAT; k++) {
                const float4 a = *(const float4*)&sm[OFF_H + k * 20 + r3];
                const float w = __ldg(&Wl1[k * LAT + jc]);
                a0 = fmaf(a.x, w, a0); a1 = fmaf(a.y, w, a1);
                a2 = fmaf(a.z, w, a2); a3 = fmaf(a.w, w, a3);
            }
            const float bb = sm[OFF_BL1 + jc];
            float d[4], iv[4];
            const float v[4] = {a0 + bb, a1 + bb, a2 + bb, a3 + bb};
#pragma unroll
            for (int i = 0; i < 4; i++) {
                const float u = fminf(fmaxf(v[i], -10.f), 10.f);
                d[i] = __expf(2.f * u) + 1.f;
            }
            rcp4(d, iv);
            sm[OFF_O1 + jc * 20 + r3 + 0] = 1.f - 2.f * iv[0];
            sm[OFF_O1 + jc * 20 + r3 + 1] = 1.f - 2.f * iv[1];
            sm[OFF_O1 + jc * 20 + r3 + 2] = 1.f - 2.f * iv[2];
            sm[OFF_O1 + jc * 20 + r3 + 3] = 1.f - 2.f * iv[3];
        }
        __syncthreads();

        // -- GEMM4: out_t = o1 @ Wl2 + bl2; warp = 4 cols, all lanes active --
        {
            const int row = lane & 15;                      // 0..15
            const int jc  = (wid << 2) + ((lane >> 4) << 1);// wid*4 + half*2
            float a0 = 0.f, a1 = 0.f;
#pragma unroll 4
            for (int k = 0; k < LAT; k++) {
                const float a = sm[OFF_O1 + k * 20 + row];
                const float2 wv = __ldg((const float2*)&Wl2[k * YD + jc]);
                a0 = fmaf(a, wv.x, a0); a1 = fmaf(a, wv.y, a1);
            }
            const float v0 = a0 + sm[OFF_BL2 + jc];
            const float v1 = a1 + sm[OFF_BL2 + jc + 1];
            if (row < nr) {
                float* op = out + (size_t)(b0 + row) * (YD * T_) + (size_t)jc * T_ + t;
                op[0]  = v0;
                op[T_] = v1;
            }
            sm[OFF_YP + jc * 17 + row]       = v0;
            sm[OFF_YP + (jc + 1) * 17 + row] = v1;
        }
        __syncthreads();
    }

    // ---- classifier: sigmoid(relu(h_T @ Wc1 + bc1) @ Wc2 + bc2) ----
    if (has_cls) {
        float* scr = sm + OFF_S0 + 4 * PSTR;                 // free after loop
        for (int idx = tid; idx < 16 * CH; idx += NT) {      // 800 = 16r x 50c
            const int r = idx & 15, c = idx >> 4;
            float acc = __ldg(&bc1[c]);
            for (int k = 0; k < LAT; k++)
                acc = fmaf(sm[OFF_H + k * 20 + r], __ldg(&Wc1[k * CH + c]), acc);
            scr[c * 16 + r] = fmaxf(acc, 0.f);
        }
        __syncthreads();
        if (tid < nr) {
            float acc = __ldg(&bc2[0]);
            for (int c = 0; c < CH; c++)
                acc = fmaf(scr[c * 16 + tid], __ldg(&Wc2[c]), acc);
            out[(size_t)B_ * YD * T_ + b0 + tid] = fsig(acc);
        }
    }
}

extern "C" void kernel_launch(void* const* d_in, const int* in_sizes, int n_in,
                              void* d_out, int out_size)
{
    cudaFuncSetAttribute(gru_kernel, cudaFuncAttributeMaxDynamicSharedMemorySize,
                         SMEM_FLOATS * (int)sizeof(float));
    const int has_cls = (out_size > B_ * YD * T_) ? 1 : 0;
    gru_kernel<<<NBK, NT, SMEM_FLOATS * sizeof(float)>>>(
        (const float*)d_in[0],   // x
        (const float*)d_in[1],   // y
        d_in[2],                 // y_mask (dtype auto-detected)
        (const float*)d_in[3],  (const float*)d_in[4],   // Wmu1, bmu1
        (const float*)d_in[5],  (const float*)d_in[6],   // Wmu2, bmu2
        (const float*)d_in[11], (const float*)d_in[12],  // Wih, bih
        (const float*)d_in[13], (const float*)d_in[14],  // Whh, bhh
        (const float*)d_in[15], (const float*)d_in[16],  // Wl1, bl1
        (const float*)d_in[17], (const float*)d_in[18],  // Wl2, bl2
        (const float*)d_in[19], (const float*)d_in[20],  // Wc1, bc1
        (const float*)d_in[21], (const float*)d_in[22],  // Wc2, bc2
        (float*)d_out, has_cls);
}